// round 2
// baseline (speedup 1.0000x reference)
#include <cuda_runtime.h>
#include <stdint.h>

// LSTM: H=50, input dim 1, T=1024, B independent batch elements.
// One block (64 threads, 50 active) per batch element.
// Thread j (< 50) owns ALL FOUR gate rows for hidden index j:
//   rows j (i), j+50 (f), j+100 (g), j+150 (o)
// so it can update c[j], h[j] locally with no inter-thread gate exchange.
// W_hh rows live in registers as f32x2 pairs (4 x 26 = 104 regs); the h
// vector is broadcast via shared memory, double-buffered so each timestep
// needs exactly ONE __syncthreads.
// Per step per thread: 13 LDS.128 + 104 fma.rn.f32x2 (8 independent chains).

#define HH 50
#define TT 1024
#define BT 64         // 2 warps; threads 50..63 idle but join barriers
#define KP 52         // H padded to multiple of 4

__device__ __forceinline__ float sigf(float x) {
    return 1.0f / (1.0f + __expf(-x));
}
__device__ __forceinline__ float tanhfast(float x) {
    // tanh(x) = 2*sigmoid(2x) - 1 (saturates correctly for large |x|)
    return fmaf(2.0f, sigf(2.0f * x), -1.0f);
}
__device__ __forceinline__ void fma2(unsigned long long& d,
                                     unsigned long long a,
                                     unsigned long long b) {
    asm("fma.rn.f32x2 %0, %1, %2, %0;" : "+l"(d) : "l"(a), "l"(b));
}
__device__ __forceinline__ unsigned long long pack2(float lo, float hi) {
    return ((unsigned long long)__float_as_uint(hi) << 32)
         |  (unsigned long long)__float_as_uint(lo);
}
__device__ __forceinline__ float sum2(unsigned long long a) {
    return __uint_as_float((unsigned)a) + __uint_as_float((unsigned)(a >> 32));
}

__global__ void __launch_bounds__(BT, 5)
lstm_kernel(const float* __restrict__ x,      // [B, T, 1]
            const float* __restrict__ W_ih,   // [200, 1]
            const float* __restrict__ W_hh,   // [200, 50]
            const float* __restrict__ b_ih,   // [200]
            const float* __restrict__ b_hh,   // [200]
            const float* __restrict__ W_lin,  // [1, 50]
            const float* __restrict__ b_lin,  // [1]
            float* __restrict__ out)          // [B, 1]
{
    __shared__ __align__(16) float h_sh[2][KP];  // double-buffered h
    __shared__ float x_sh[TT];

    const int j = threadIdx.x;
    const int b = blockIdx.x;

    // Stage this batch element's x row.
    for (int i = j; i < TT; i += BT) x_sh[i] = x[(size_t)b * TT + i];
    if (j < KP) { h_sh[0][j] = 0.0f; h_sh[1][j] = 0.0f; }  // h0=0; pad stays 0

    // Per-thread weights: 4 gate rows, packed f32x2.
    unsigned long long wp[4][KP / 2];
    float wih[4], bias[4];
    if (j < HH) {
        #pragma unroll
        for (int r = 0; r < 4; r++) {
            const int row = j + r * HH;
            wih[r]  = W_ih[row];
            bias[r] = b_ih[row] + b_hh[row];
            #pragma unroll
            for (int q = 0; q < KP / 2; q++) {
                float lo = (2 * q     < HH) ? W_hh[row * HH + 2 * q]     : 0.0f;
                float hi = (2 * q + 1 < HH) ? W_hh[row * HH + 2 * q + 1] : 0.0f;
                wp[r][q] = pack2(lo, hi);
            }
        }
    }
    float c = 0.0f;
    __syncthreads();

    #pragma unroll 1
    for (int t = 0; t < TT; t++) {
        const int rb = t & 1;        // read buffer (t=0 reads zeros)
        if (j < HH) {
            const float xt = x_sh[t];
            unsigned long long a0[4], a1[4];
            #pragma unroll
            for (int r = 0; r < 4; r++) {
                a0[r] = (unsigned long long)
                        __float_as_uint(fmaf(xt, wih[r], bias[r]));
                a1[r] = 0ull;
            }
            const ulonglong2* h2 = (const ulonglong2*)h_sh[rb];
            #pragma unroll
            for (int q = 0; q < 13; q++) {
                ulonglong2 hv = h2[q];             // LDS.128 broadcast
                #pragma unroll
                for (int r = 0; r < 4; r++) {
                    fma2(a0[r], wp[r][2 * q],     hv.x);
                    fma2(a1[r], wp[r][2 * q + 1], hv.y);
                }
            }
            const float gi = sigf(sum2(a0[0]) + sum2(a1[0]));
            const float gf = sigf(sum2(a0[1]) + sum2(a1[1]));
            const float gg = tanhfast(sum2(a0[2]) + sum2(a1[2]));
            const float go = sigf(sum2(a0[3]) + sum2(a1[3]));
            c = fmaf(gf, c, gi * gg);
            h_sh[rb ^ 1][j] = go * tanhfast(c);    // write buffer
        }
        __syncthreads();   // separates this write from next step's reads AND
                           // previous reads of the write buffer from this write
    }

    // Final h is in the buffer written at t=1023: (1023&1)^1 = 0.
    if (j == 0) {
        float s = b_lin[0];
        #pragma unroll 1
        for (int k = 0; k < HH; k++) s = fmaf(h_sh[0][k], W_lin[k], s);
        out[b] = s;
    }
}

extern "C" void kernel_launch(void* const* d_in, const int* in_sizes, int n_in,
                              void* d_out, int out_size) {
    const float* x     = (const float*)d_in[0];
    const float* W_ih  = (const float*)d_in[1];
    const float* W_hh  = (const float*)d_in[2];
    const float* b_ih  = (const float*)d_in[3];
    const float* b_hh  = (const float*)d_in[4];
    const float* W_lin = (const float*)d_in[5];
    const float* b_lin = (const float*)d_in[6];
    float* out = (float*)d_out;

    int B = in_sizes[0] / TT;
    lstm_kernel<<<B, BT>>>(x, W_ih, W_hh, b_ih, b_hh, W_lin, b_lin, out);
}

// round 3
// speedup vs baseline: 1.1779x; 1.1779x over previous
#include <cuda_runtime.h>
#include <stdint.h>

// LSTM: H=50, input dim 1, T=1024, B independent batch elements.
// One block (224 threads, 7 warps) per batch element.
// Lanes 4k..4k+3 of warp w jointly own hidden index j = w*8 + k:
//   lane r computes ALL FOUR gate rows (i,f,g,o) restricted to h-chunk
//   [16r, 16r+16)  (h padded to 64 with zeros).
// Cross-lane: 3-shfl targeted reduction gives lane r the full sum for gate r;
// lane r applies its activation; 3 more shfls hand all four activated gates
// to lane r==0, which updates c and writes h. Double-buffered h in shared
// => exactly ONE __syncthreads per timestep, no shared gate traffic.
// Per thread per step: 4 LDS.128 + 32 fma.rn.f32x2 + 6 shfl + 1-2 sigmoid.

#define HH 50
#define TT 1024
#define BT 224        // 7 warps; 8 hidden idx per warp; 56 slots >= 50
#define HP 64         // h padded to 64 floats (chunks of 16 per lane)

typedef unsigned long long ull;

__device__ __forceinline__ float sigf(float x) {
    return 1.0f / (1.0f + __expf(-x));
}
__device__ __forceinline__ void fma2(ull& d, ull a, ull b) {
    asm("fma.rn.f32x2 %0, %1, %2, %0;" : "+l"(d) : "l"(a), "l"(b));
}
__device__ __forceinline__ ull pack2(float lo, float hi) {
    return ((ull)__float_as_uint(hi) << 32) | (ull)__float_as_uint(lo);
}
__device__ __forceinline__ float sum2(ull a) {
    return __uint_as_float((unsigned)a) + __uint_as_float((unsigned)(a >> 32));
}

__global__ void __launch_bounds__(BT, 3)
lstm_kernel(const float* __restrict__ x,      // [B, T, 1]
            const float* __restrict__ W_ih,   // [200, 1]
            const float* __restrict__ W_hh,   // [200, 50]
            const float* __restrict__ b_ih,   // [200]
            const float* __restrict__ b_hh,   // [200]
            const float* __restrict__ W_lin,  // [1, 50]
            const float* __restrict__ b_lin,  // [1]
            float* __restrict__ out)          // [B, 1]
{
    __shared__ __align__(16) float h_sh[2][HP];   // double-buffered h
    __shared__ float x_sh[TT];

    const int tid  = threadIdx.x;
    const int lane = tid & 31;
    const int r    = lane & 3;        // sub-lane: gate owner + h-chunk
    const int k    = lane >> 2;       // idx within warp (0..7)
    const int j    = (tid >> 5) * 8 + k;    // hidden index (may be >= 50)
    const bool active = (j < HH);
    const bool owner  = active && (r == 0);
    const int b = blockIdx.x;

    for (int i = tid; i < TT; i += BT) x_sh[i] = x[(size_t)b * TT + i];
    if (tid < HP) { h_sh[0][tid] = 0.0f; h_sh[1][tid] = 0.0f; }

    // Weights: 4 gate rows x 16 cols (this lane's chunk), packed f32x2.
    ull wp[4][8];
    #pragma unroll
    for (int g = 0; g < 4; g++) {
        const int row = g * HH + j;
        #pragma unroll
        for (int q = 0; q < 8; q++) {
            const int col = 16 * r + 2 * q;
            float lo = (active && col     < HH) ? W_hh[row * HH + col]     : 0.0f;
            float hi = (active && col + 1 < HH) ? W_hh[row * HH + col + 1] : 0.0f;
            wp[g][q] = pack2(lo, hi);
        }
    }
    // Gate-r bias/input weight for this lane's own gate.
    float wihr = 0.0f, biasr = 0.0f;
    if (active) {
        const int row = r * HH + j;
        wihr  = W_ih[row];
        biasr = b_ih[row] + b_hh[row];
    }
    // Activation params: lane r==2 owns gate g -> tanh(x) = 2*sig(2x)-1.
    const float am = (r == 2) ? 2.0f : 1.0f;
    const float ad = (r == 2) ? -1.0f : 0.0f;
    float c = 0.0f;
    __syncthreads();

    #pragma unroll 2
    for (int t = 0; t < TT; t++) {
        const float xt = x_sh[t];
        const ulonglong2* h2 =
            (const ulonglong2*)(&h_sh[t & 1][r * 16]);   // this lane's chunk
        ull a[4] = {0ull, 0ull, 0ull, 0ull};
        #pragma unroll
        for (int q = 0; q < 4; q++) {
            ulonglong2 hv = h2[q];                       // LDS.128
            #pragma unroll
            for (int g = 0; g < 4; g++) {
                fma2(a[g], wp[g][2 * q],     hv.x);
                fma2(a[g], wp[g][2 * q + 1], hv.y);
            }
        }
        const float s0 = sum2(a[0]), s1 = sum2(a[1]),
                    s2 = sum2(a[2]), s3 = sum2(a[3]);
        // Targeted 4-lane reduction: lane r ends with full sum of gate r.
        // Lane sends s[r^m] to partner (lane^m), receives partner's s[r].
        const bool b0 = (r & 1) != 0, b1 = (r & 2) != 0;
        const float send1 = b1 ? (b0 ? s2 : s3) : (b0 ? s0 : s1);  // s[r^1]
        const float send2 = b1 ? (b0 ? s1 : s0) : (b0 ? s3 : s2);  // s[r^2]
        const float send3 = b1 ? (b0 ? s0 : s1) : (b0 ? s2 : s3);  // s[r^3]
        const float own   = b1 ? (b0 ? s3 : s2) : (b0 ? s1 : s0);  // s[r]
        float tot = own
                  + __shfl_xor_sync(0xFFFFFFFFu, send1, 1)
                  + __shfl_xor_sync(0xFFFFFFFFu, send2, 2)
                  + __shfl_xor_sync(0xFFFFFFFFu, send3, 3);
        tot += fmaf(xt, wihr, biasr);
        // Lane r activates gate r (r==2 -> tanh, else sigmoid).
        const float v = fmaf(am, sigf(am * tot), ad);
        // Hand all four activated gates to the owner lane (r==0).
        const float e1 = __shfl_xor_sync(0xFFFFFFFFu, v, 1);   // gate r^1
        const float e2 = __shfl_xor_sync(0xFFFFFFFFu, v, 2);   // gate r^2
        const float e3 = __shfl_xor_sync(0xFFFFFFFFu, e1, 2);  // gate r^3
        if (owner) {
            // owner: v=i, e1=f, e2=g, e3=o
            c = fmaf(e1, c, v * e2);
            const float th = fmaf(2.0f, sigf(2.0f * c), -1.0f); // tanh(c)
            h_sh[(t & 1) ^ 1][j] = e3 * th;
        }
        __syncthreads();
    }

    // Final h is in buffer (1023&1)^1 == 0. Linear head.
    if (tid == 0) {
        float s = b_lin[0];
        #pragma unroll 1
        for (int q = 0; q < HH; q++) s = fmaf(h_sh[0][q], W_lin[q], s);
        out[b] = s;
    }
}

extern "C" void kernel_launch(void* const* d_in, const int* in_sizes, int n_in,
                              void* d_out, int out_size) {
    const float* x     = (const float*)d_in[0];
    const float* W_ih  = (const float*)d_in[1];
    const float* W_hh  = (const float*)d_in[2];
    const float* b_ih  = (const float*)d_in[3];
    const float* b_hh  = (const float*)d_in[4];
    const float* W_lin = (const float*)d_in[5];
    const float* b_lin = (const float*)d_in[6];
    float* out = (float*)d_out;

    int B = in_sizes[0] / TT;
    lstm_kernel<<<B, BT>>>(x, W_ih, W_hh, b_ih, b_hh, W_lin, b_lin, out);
}